// round 3
// baseline (speedup 1.0000x reference)
#include <cuda_runtime.h>

#define B_  16
#define C_  64
#define H_  224
#define W_  224
#define O_  128
#define PH_ 16
#define OH_ 222
#define OW_ 222

#define NCH 8          // pipeline chunks
#define CB  (B_/NCH)   // batches per chunk = 2

__device__ float g_s[(size_t)B_ * H_ * W_];

// Streams/events created at static-init (before harness checkpoints / capture).
struct PipeRes {
    cudaStream_t s1;
    cudaEvent_t fork[NCH], join;
    PipeRes() {
        cudaStreamCreateWithFlags(&s1, cudaStreamNonBlocking);
        for (int i = 0; i < NCH; i++)
            cudaEventCreateWithFlags(&fork[i], cudaEventDisableTiming);
        cudaEventCreateWithFlags(&join, cudaEventDisableTiming);
    }
};
static PipeRes g_pipe;

// ================= Kernel 1: channel reduction (float4) =================
// block = 224 threads = 4 rows x 56 float4-cols; grid = CB*56 per chunk
__global__ __launch_bounds__(224) void k1_reduce_c(
    const float* __restrict__ x,
    const float* __restrict__ pw,
    const float* __restrict__ pb,
    int b0)
{
    const int blk = blockIdx.x;
    const int b   = b0 + blk / (H_ / 4);
    const int h0  = (blk % (H_ / 4)) * 4;

    __shared__ float4 pws[4][C_][4];
    __shared__ float4 bsum[4][4];

    const int t = threadIdx.x;

    const float4* pw4 = (const float4*)pw;
    for (int idx = t; idx < 4 * C_ * 4; idx += 224) {
        int rr = idx >> 8;
        int c  = (idx >> 2) & (C_ - 1);
        int w4 = idx & 3;
        int hh = (h0 + rr) & (PH_ - 1);
        pws[rr][c][w4] = pw4[c * 64 + hh * 4 + w4];
    }
    if (t < 16) {
        int rr = t >> 2, w4 = t & 3;
        int hh = (h0 + rr) & (PH_ - 1);
        const float4* pb4 = (const float4*)pb;
        float4 s = make_float4(0.f, 0.f, 0.f, 0.f);
        #pragma unroll 8
        for (int c = 0; c < C_; c++) {
            float4 v = pb4[c * 64 + hh * 4 + w4];
            s.x += v.x; s.y += v.y; s.z += v.z; s.w += v.w;
        }
        bsum[rr][w4] = s;
    }
    __syncthreads();

    const int r      = t / 56;
    const int lane_w = t % 56;
    const int w4     = lane_w & 3;
    const int h      = h0 + r;

    const float4* xp = (const float4*)x + ((size_t)b * C_ * H_ + h) * 56 + lane_w;

    float4 acc = bsum[r][w4];
    #pragma unroll 16
    for (int c = 0; c < C_; c++) {
        float4 xv = __ldg(xp + (size_t)c * (H_ * 56));
        float4 wv = pws[r][c][w4];
        acc.x = fmaf(xv.x, wv.x, acc.x);
        acc.y = fmaf(xv.y, wv.y, acc.y);
        acc.z = fmaf(xv.z, wv.z, acc.z);
        acc.w = fmaf(xv.w, wv.w, acc.w);
    }
    ((float4*)g_s)[((size_t)b * H_ + h) * 56 + lane_w] = acc;
}

// ================= Kernel 2: 3x3 conv, 128 shared-channel filters =================
#define OCG 32
__global__ __launch_bounds__(224) void k2_conv3x3(
    const float* __restrict__ comp,
    float* __restrict__ out,
    int b0)
{
    const int gx = blockIdx.x;
    const int b  = b0 + gx / (OH_ / 2);
    const int i0 = (gx % (OH_ / 2)) * 2;
    const int o0 = blockIdx.y * OCG;

    __shared__ float srow[4][W_];
    __shared__ float csh[OCG * 12];

    const int t = threadIdx.x;

    const float* sp = g_s + ((size_t)b * H_ + i0) * W_;
    #pragma unroll
    for (int k = 0; k < 4; k++)
        srow[k][t] = sp[k * W_ + t];
    for (int idx = t; idx < OCG * 9; idx += 224) {
        int k = idx / 9, m = idx % 9;
        csh[k * 12 + m] = comp[(o0 + k) * 9 + m];
    }
    __syncthreads();

    const int r  = t / 112;
    const int q  = t % 112;
    if (q >= 111) return;
    const int j0 = q * 2;
    const int i  = i0 + r;

    float2 va[3], vb[3];
    #pragma unroll
    for (int d = 0; d < 3; d++) {
        va[d] = *(const float2*)&srow[r + d][j0];
        vb[d] = *(const float2*)&srow[r + d][j0 + 2];
    }

    const float4* csh4 = (const float4*)csh;
    size_t base = (((size_t)b * O_ + o0) * OH_ + i) * OW_ + j0;

    #pragma unroll 8
    for (int k = 0; k < OCG; k++) {
        float4 w0 = csh4[k * 3 + 0];
        float4 w1 = csh4[k * 3 + 1];
        float4 w2 = csh4[k * 3 + 2];

        float ax, ay;
        ax = w0.x * va[0].x; ay = w0.x * va[0].y;
        ax = fmaf(w0.y, va[0].y, ax); ay = fmaf(w0.y, vb[0].x, ay);
        ax = fmaf(w0.z, vb[0].x, ax); ay = fmaf(w0.z, vb[0].y, ay);

        ax = fmaf(w0.w, va[1].x, ax); ay = fmaf(w0.w, va[1].y, ay);
        ax = fmaf(w1.x, va[1].y, ax); ay = fmaf(w1.x, vb[1].x, ay);
        ax = fmaf(w1.y, vb[1].x, ax); ay = fmaf(w1.y, vb[1].y, ay);

        ax = fmaf(w1.z, va[2].x, ax); ay = fmaf(w1.z, va[2].y, ay);
        ax = fmaf(w1.w, va[2].y, ax); ay = fmaf(w1.w, vb[2].x, ay);
        ax = fmaf(w2.x, vb[2].x, ax); ay = fmaf(w2.x, vb[2].y, ay);

        *(float2*)(out + base + (size_t)k * (OH_ * OW_)) = make_float2(ax, ay);
    }
}

extern "C" void kernel_launch(void* const* d_in, const int* in_sizes, int n_in,
                              void* d_out, int out_size)
{
    const float* x    = (const float*)d_in[0];
    const float* pw   = (const float*)d_in[1];
    const float* pb   = (const float*)d_in[2];
    const float* comp = (const float*)d_in[3];
    float* out = (float*)d_out;

    dim3 g1(CB * (H_ / 4));
    dim3 g2(CB * (OH_ / 2), O_ / OCG);

    for (int ch = 0; ch < NCH; ch++) {
        int b0 = ch * CB;
        // producer chunk on the launch stream
        k1_reduce_c<<<g1, 224>>>(x, pw, pb, b0);
        // fork: consumer chunk on side stream after its producer completes
        cudaEventRecord(g_pipe.fork[ch], 0);
        cudaStreamWaitEvent(g_pipe.s1, g_pipe.fork[ch], 0);
        k2_conv3x3<<<g2, 224, 0, g_pipe.s1>>>(comp, out, b0);
    }
    // join back to the launch stream
    cudaEventRecord(g_pipe.join, g_pipe.s1);
    cudaStreamWaitEvent(0, g_pipe.join, 0);
}

// round 4
// speedup vs baseline: 1.9833x; 1.9833x over previous
#include <cuda_runtime.h>

#define B_  16
#define C_  64
#define H_  224
#define W_  224
#define O_  128
#define PH_ 16
#define OH_ 222
#define OW_ 222

#define SR   6                 // output rows per strip
#define NSTR 37                // 222 / 6
#define SROWS 8                // s rows needed per strip (SR + 2)
#define NTHR 224

// ======================= Fused kernel =======================
// grid.x = B * NSTR = 592, block = 224 threads
// Phase A: compute s[8][224] (channel reduction) into SMEM
// Phase B: 3x3 conv of s against all 128 shared-channel filters
__global__ __launch_bounds__(NTHR) void k_fused(
    const float* __restrict__ x,
    const float* __restrict__ pw,
    const float* __restrict__ pb,
    const float* __restrict__ comp,
    float* __restrict__ out)
{
    const int b  = blockIdx.x / NSTR;
    const int i0 = (blockIdx.x % NSTR) * SR;

    __shared__ float s[SROWS][W_];      // 7 KB
    __shared__ float csh[O_ * 12];      // 6 KB (9 weights padded to 12)
    __shared__ float bsum_s[256];       // sum_c pb[c][hh][ww]

    const int t = threadIdx.x;

    // ---- stage compressor weights ----
    for (int idx = t; idx < O_ * 9; idx += NTHR) {
        int o = idx / 9, m = idx % 9;
        csh[o * 12 + m] = comp[idx];
    }
    // ---- bias channel-sum (pb is tiny & L2-hot; redundant per block is free) ----
    for (int idx = t; idx < 256; idx += NTHR) {
        float acc = 0.f;
        #pragma unroll 16
        for (int c = 0; c < C_; c++)
            acc += __ldg(pb + c * 256 + idx);
        bsum_s[idx] = acc;
    }
    __syncthreads();

    // ---- Phase A: channel reduction into s ----
    // 448 float4 positions = 8 rows x 56 float4-cols; 2 per thread
    const float4* x4  = (const float4*)x + (size_t)b * C_ * H_ * 56;
    const float4* pw4 = (const float4*)pw;
    const float4* bs4 = (const float4*)bsum_s;

    #pragma unroll
    for (int p = t; p < SROWS * 56; p += NTHR) {
        const int r  = p / 56;
        const int lw = p % 56;
        const int h  = i0 + r;
        const int hh = h & (PH_ - 1);
        const int w4 = lw & 3;

        const float4* xp = x4 + (size_t)h * 56 + lw;
        float4 acc = bs4[hh * 4 + w4];
        #pragma unroll 16
        for (int c = 0; c < C_; c++) {
            float4 xv = __ldg(xp + (size_t)c * (H_ * 56));
            float4 wv = __ldg(pw4 + c * 64 + hh * 4 + w4);
            acc.x = fmaf(xv.x, wv.x, acc.x);
            acc.y = fmaf(xv.y, wv.y, acc.y);
            acc.z = fmaf(xv.z, wv.z, acc.z);
            acc.w = fmaf(xv.w, wv.w, acc.w);
        }
        *(float4*)&s[r][lw * 4] = acc;
    }
    __syncthreads();

    // ---- Phase B: 3x3 conv, all 128 output channels ----
    // thread -> (rp = row parity 0/1, q = column pair); rows rp, rp+2, rp+4
    const int q  = t % 112;
    const int rp = t / 112;
    if (q >= 111) return;
    const int j0 = q * 2;

    // preload the 7 s-rows window for this column pair into registers
    float2 wa[7], wb[7];
    #pragma unroll
    for (int d = 0; d < 7; d++) {
        wa[d] = *(const float2*)&s[rp + d][j0];
        wb[d] = *(const float2*)&s[rp + d][j0 + 2];
    }

    const float4* c4 = (const float4*)csh;
    size_t base = (((size_t)b * O_) * OH_ + (i0 + rp)) * OW_ + j0;

    #pragma unroll 4
    for (int o = 0; o < O_; o++) {
        float4 w0 = c4[o * 3 + 0];   // w[0..3]
        float4 w1 = c4[o * 3 + 1];   // w[4..7]
        float4 w2 = c4[o * 3 + 2];   // w[8], pad

        #pragma unroll
        for (int k = 0; k < 3; k++) {
            const float2 a0 = wa[2 * k],     b0 = wb[2 * k];
            const float2 a1 = wa[2 * k + 1], b1 = wb[2 * k + 1];
            const float2 a2 = wa[2 * k + 2], b2 = wb[2 * k + 2];

            float ax, ay;
            ax = w0.x * a0.x;             ay = w0.x * a0.y;
            ax = fmaf(w0.y, a0.y, ax);    ay = fmaf(w0.y, b0.x, ay);
            ax = fmaf(w0.z, b0.x, ax);    ay = fmaf(w0.z, b0.y, ay);

            ax = fmaf(w0.w, a1.x, ax);    ay = fmaf(w0.w, a1.y, ay);
            ax = fmaf(w1.x, a1.y, ax);    ay = fmaf(w1.x, b1.x, ay);
            ax = fmaf(w1.y, b1.x, ax);    ay = fmaf(w1.y, b1.y, ay);

            ax = fmaf(w1.z, a2.x, ax);    ay = fmaf(w1.z, a2.y, ay);
            ax = fmaf(w1.w, a2.y, ax);    ay = fmaf(w1.w, b2.x, ay);
            ax = fmaf(w2.x, b2.x, ax);    ay = fmaf(w2.x, b2.y, ay);

            *(float2*)(out + base + (size_t)k * (2 * OW_)) = make_float2(ax, ay);
        }
        base += (size_t)OH_ * OW_;
    }
}

extern "C" void kernel_launch(void* const* d_in, const int* in_sizes, int n_in,
                              void* d_out, int out_size)
{
    const float* x    = (const float*)d_in[0];
    const float* pw   = (const float*)d_in[1];
    const float* pb   = (const float*)d_in[2];
    const float* comp = (const float*)d_in[3];
    float* out = (float*)d_out;

    k_fused<<<B_ * NSTR, NTHR>>>(x, pw, pb, comp, out);
}

// round 5
// speedup vs baseline: 2.0394x; 1.0282x over previous
#include <cuda_runtime.h>

#define B_  16
#define C_  64
#define H_  224
#define W_  224
#define O_  128
#define OH_ 222
#define OW_ 222
#define SR    6
#define SROWS 8
#define NSTR  37
#define NTHR  224
#define HW56  (H_ * 56)

typedef unsigned long long ull;

__device__ __forceinline__ ull mul2(ull a, ull b) {
    ull d; asm("mul.rn.f32x2 %0,%1,%2;" : "=l"(d) : "l"(a), "l"(b)); return d;
}
__device__ __forceinline__ ull fma2(ull a, ull b, ull c) {
    ull d; asm("fma.rn.f32x2 %0,%1,%2,%3;" : "=l"(d) : "l"(a), "l"(b), "l"(c)); return d;
}
__device__ __forceinline__ ull packf2(float lo, float hi) {
    ull d; asm("mov.b64 %0,{%1,%2};" : "=l"(d) : "f"(lo), "f"(hi)); return d;
}

struct SM {
    float s[2][SROWS][W_];        // double-buffered s strips (14 KB)
    ulonglong2 wsh[O_][5];        // weights as duplicated f32 pairs, 10 pairs/o (10 KB)
    float bsum[256];              // sum_c pb
};

// B-phase inner body for one output channel o (packed f32x2, 2 cols x 3 rows)
#define CONV_O(o, obase)                                               \
    {                                                                  \
        ulonglong2 w01 = sm.wsh[o][0], w23 = sm.wsh[o][1];             \
        ulonglong2 w45 = sm.wsh[o][2], w67 = sm.wsh[o][3];             \
        ulonglong2 w8x = sm.wsh[o][4];                                 \
        float* obp = out + (obase) + (size_t)(o) * (OH_ * OW_);        \
        _Pragma("unroll")                                              \
        for (int k = 0; k < 3; k++) {                                  \
            ull acc = mul2(w01.x, P[2*k][0]);                          \
            acc = fma2(w01.y, P[2*k][1], acc);                         \
            acc = fma2(w23.x, P[2*k][2], acc);                         \
            acc = fma2(w23.y, P[2*k+1][0], acc);                       \
            acc = fma2(w45.x, P[2*k+1][1], acc);                       \
            acc = fma2(w45.y, P[2*k+1][2], acc);                       \
            acc = fma2(w67.x, P[2*k+2][0], acc);                       \
            acc = fma2(w67.y, P[2*k+2][1], acc);                       \
            acc = fma2(w8x.x, P[2*k+2][2], acc);                       \
            *(ull*)(obp + k * 2 * OW_) = acc;                          \
        }                                                              \
    }

#define LOAD_P(buf)                                                    \
    _Pragma("unroll")                                                  \
    for (int d = 0; d < 7; d++) {                                      \
        float2 lo = *(const float2*)&sm.s[buf][rp + d][j0];            \
        float2 hi = *(const float2*)&sm.s[buf][rp + d][j0 + 2];        \
        P[d][0] = packf2(lo.x, lo.y);                                  \
        P[d][1] = packf2(lo.y, hi.x);                                  \
        P[d][2] = packf2(hi.x, hi.y);                                  \
    }

// grid = 296 blocks (2/SM), each handles 2 consecutive strips, pipelined.
__global__ __launch_bounds__(NTHR, 2) void k_fused(
    const float* __restrict__ x,
    const float* __restrict__ pw,
    const float* __restrict__ pb,
    const float* __restrict__ comp,
    float* __restrict__ out)
{
    __shared__ SM sm;
    const int t = threadIdx.x;

    const int st0 = 2 * blockIdx.x;
    const int b0 = st0 / NSTR, i00 = (st0 % NSTR) * SR;
    const int st1 = st0 + 1;
    const int b1 = st1 / NSTR, i01 = (st1 % NSTR) * SR;

    // ---- prologue: stage duplicated weight pairs + bias channel-sum ----
    for (int idx = t; idx < O_ * 10; idx += NTHR) {
        int m = idx % 10;
        float w = (m < 9) ? comp[(idx / 10) * 9 + m] : 0.f;
        ((float2*)sm.wsh)[idx] = make_float2(w, w);
    }
    for (int idx = t; idx < 256; idx += NTHR) {
        float a = 0.f;
        #pragma unroll 16
        for (int c = 0; c < C_; c++) a += __ldg(pb + c * 256 + idx);
        sm.bsum[idx] = a;
    }
    __syncthreads();

    // A-phase thread geometry (2 positions: rows r0 and r0+4, same float4 col)
    const int r0 = t / 56, lw = t % 56, w4 = lw & 3;
    const float4* pw4 = (const float4*)pw;
    const float4* bs4 = (const float4*)sm.bsum;

    // ---- phase A (plain) for strip0 -> s[0] ----
    {
        const float4* x4b = (const float4*)x + (size_t)b0 * C_ * HW56;
        const int h0 = i00 + r0, h1 = h0 + 4;
        const int hh0 = h0 & 15, hh1 = h1 & 15;
        const float4* xp0 = x4b + (size_t)h0 * 56 + lw;
        const float4* xp1 = x4b + (size_t)h1 * 56 + lw;
        const float4* pw0 = pw4 + hh0 * 4 + w4;
        const float4* pw1 = pw4 + hh1 * 4 + w4;
        float4 ba = bs4[hh0 * 4 + w4], bb = bs4[hh1 * 4 + w4];
        ull a00 = packf2(ba.x, ba.y), a01 = packf2(ba.z, ba.w);
        ull a10 = packf2(bb.x, bb.y), a11 = packf2(bb.z, bb.w);
        #pragma unroll 8
        for (int c = 0; c < C_; c++) {
            float4 xv0 = __ldg(xp0 + (size_t)c * HW56);
            float4 xv1 = __ldg(xp1 + (size_t)c * HW56);
            float4 wv0 = __ldg(pw0 + c * 64);
            float4 wv1 = __ldg(pw1 + c * 64);
            a00 = fma2(packf2(xv0.x, xv0.y), packf2(wv0.x, wv0.y), a00);
            a01 = fma2(packf2(xv0.z, xv0.w), packf2(wv0.z, wv0.w), a01);
            a10 = fma2(packf2(xv1.x, xv1.y), packf2(wv1.x, wv1.y), a10);
            a11 = fma2(packf2(xv1.z, xv1.w), packf2(wv1.z, wv1.w), a11);
        }
        ull* d0 = (ull*)&sm.s[0][r0][lw * 4];     d0[0] = a00; d0[1] = a01;
        ull* d1 = (ull*)&sm.s[0][r0 + 4][lw * 4]; d1[0] = a10; d1[1] = a11;
    }
    __syncthreads();

    // B-phase thread geometry
    const int q = t % 112, rp = t / 112;
    const int j0 = 2 * q;
    const bool doB = (q < 111);
    ull P[7][3];

    // ---- fused: B(strip0 from s[0]) interleaved with A(strip1) -> s[1] ----
    if (doB) { LOAD_P(0); }

    const float4* x4b1 = (const float4*)x + (size_t)b1 * C_ * HW56;
    const int h10 = i01 + r0, h11 = h10 + 4;
    const int hh10 = h10 & 15, hh11 = h11 & 15;
    const float4* xq0 = x4b1 + (size_t)h10 * 56 + lw;
    const float4* xq1 = x4b1 + (size_t)h11 * 56 + lw;
    const float4* pwq0 = pw4 + hh10 * 4 + w4;
    const float4* pwq1 = pw4 + hh11 * 4 + w4;
    float4 ba = bs4[hh10 * 4 + w4], bb = bs4[hh11 * 4 + w4];
    ull a00 = packf2(ba.x, ba.y), a01 = packf2(ba.z, ba.w);
    ull a10 = packf2(bb.x, bb.y), a11 = packf2(bb.z, bb.w);

    const size_t ob0 = (((size_t)b0 * O_) * OH_ + (i00 + rp)) * OW_ + j0;

    #pragma unroll 1
    for (int og = 0; og < 16; og++) {
        // issue next-strip x loads (4 channels x 2 positions) — latency hidden by B chunk
        float4 xv0[4], xv1[4];
        #pragma unroll
        for (int cc = 0; cc < 4; cc++) {
            int c = og * 4 + cc;
            xv0[cc] = __ldg(xq0 + (size_t)c * HW56);
            xv1[cc] = __ldg(xq1 + (size_t)c * HW56);
        }
        // B chunk: 8 output channels
        if (doB) {
            #pragma unroll
            for (int oo = 0; oo < 8; oo++) {
                CONV_O(og * 8 + oo, ob0)
            }
        }
        // consume the loads
        #pragma unroll
        for (int cc = 0; cc < 4; cc++) {
            int c = og * 4 + cc;
            float4 wv0 = __ldg(pwq0 + c * 64);
            float4 wv1 = __ldg(pwq1 + c * 64);
            a00 = fma2(packf2(xv0[cc].x, xv0[cc].y), packf2(wv0.x, wv0.y), a00);
            a01 = fma2(packf2(xv0[cc].z, xv0[cc].w), packf2(wv0.z, wv0.w), a01);
            a10 = fma2(packf2(xv1[cc].x, xv1[cc].y), packf2(wv1.x, wv1.y), a10);
            a11 = fma2(packf2(xv1[cc].z, xv1[cc].w), packf2(wv1.z, wv1.w), a11);
        }
    }
    {
        ull* d0 = (ull*)&sm.s[1][r0][lw * 4];     d0[0] = a00; d0[1] = a01;
        ull* d1 = (ull*)&sm.s[1][r0 + 4][lw * 4]; d1[0] = a10; d1[1] = a11;
    }
    __syncthreads();

    // ---- plain B for strip1 from s[1] ----
    if (doB) {
        LOAD_P(1);
        const size_t ob1 = (((size_t)b1 * O_) * OH_ + (i01 + rp)) * OW_ + j0;
        #pragma unroll 4
        for (int o = 0; o < O_; o++) {
            CONV_O(o, ob1)
        }
    }
}

extern "C" void kernel_launch(void* const* d_in, const int* in_sizes, int n_in,
                              void* d_out, int out_size)
{
    const float* x    = (const float*)d_in[0];
    const float* pw   = (const float*)d_in[1];
    const float* pb   = (const float*)d_in[2];
    const float* comp = (const float*)d_in[3];
    float* out = (float*)d_out;

    k_fused<<<(B_ * NSTR) / 2, NTHR>>>(x, pw, pb, comp, out);
}